// round 9
// baseline (speedup 1.0000x reference)
#include <cuda_runtime.h>
#include <cuda_bf16.h>
#include <cstdint>

#define CIN  64
#define COUT 64
#define KTAP 9
#define EPS_BN 1e-4f
#define LEAK 0.333f
#define MAX_N 1000000
#define TILE_M 128

// ---------------- global scratch ----------------
__device__ float g_y[(size_t)MAX_N * COUT];
__device__ float g_sum[COUT];
__device__ float g_ssq[COUT];
__device__ float g_scale[COUT];
__device__ float g_bias[COUT];
__device__ int   g_valid_u8;
// W as tf32, layout [tap][ks][n][p*2+e] : k = ks*8 + e*4 + p
__device__ uint32_t g_wtf[KTAP * 4096];

// ---------------- PTX helpers (portable sm_80-level only) ----------------
__device__ __forceinline__ uint32_t f2tf32(float x) {
    uint32_t u;
    asm("cvt.rna.tf32.f32 %0, %1;" : "=r"(u) : "f"(x));
    return u;
}
__device__ __forceinline__ void mma_tf32(float* c, uint32_t a0, uint32_t a1,
                                         uint32_t a2, uint32_t a3,
                                         uint32_t b0, uint32_t b1) {
    asm volatile(
        "mma.sync.aligned.m16n8k8.row.col.f32.tf32.tf32.f32 "
        "{%0,%1,%2,%3}, {%4,%5,%6,%7}, {%8,%9}, {%0,%1,%2,%3};"
        : "+f"(c[0]), "+f"(c[1]), "+f"(c[2]), "+f"(c[3])
        : "r"(a0), "r"(a1), "r"(a2), "r"(a3), "r"(b0), "r"(b1));
}

// ---------------- kernel: init (zero stats + detect valid dtype) ----------------
__global__ void init_kernel(const unsigned int* __restrict__ vwords, int nwords) {
    __shared__ int s_flag;
    int t = threadIdx.x;
    if (t == 0) s_flag = 0;
    if (t < COUT) { g_sum[t] = 0.0f; g_ssq[t] = 0.0f; }
    __syncthreads();
    int local = 0;
    for (int i = t; i < nwords; i += blockDim.x) {
        unsigned int w = vwords[i];
        if (w != 0u && w != 1u && w != 0x3F800000u) local = 1;
    }
    if (local) atomicOr(&s_flag, 1);
    __syncthreads();
    if (t == 0) g_valid_u8 = s_flag;
}

// ---------------- kernel: prep W (transpose + tf32 round + k-pair layout) ----------------
__global__ void prep_w_kernel(const float* __restrict__ W) {
    int i = blockIdx.x * blockDim.x + threadIdx.x;
    if (i >= KTAP * CIN * COUT) return;
    int t = i / (CIN * COUT);
    int rem = i % (CIN * COUT);
    int k = rem / COUT;           // ci
    int n = rem % COUT;
    int ks = k >> 3, r = k & 7, p = r & 3, e = r >> 2;
    g_wtf[t * 4096 + (ks * 64 + n) * 8 + p * 2 + e] = f2tf32(W[i]);
}

// ---------------- pad kernel (slot so ncu -s5 captures conv) ----------------
__global__ void pad_kernel() {}

// ---------------- kernel: conv (mma.sync tf32, vectorized swizzled staging) ----------------
#define W_BYTES   (KTAP * 16384)               // 147456
#define SMEM_A    W_BYTES
#define APLANE    32768                         // [8 ks][128 row][32B cell]
#define CONV_SMEM (SMEM_A + 2 * APLANE)         // 212992

__global__ void __launch_bounds__(256, 1)
conv_kernel(const float* __restrict__ feats,
            const int* __restrict__ nidx,
            const void* __restrict__ validp,
            int N, int ntiles) {
    extern __shared__ char smem[];
    __shared__ float s_sum[COUT];
    __shared__ float s_ssq[COUT];

    const int tid = threadIdx.x, warp = tid >> 5, lane = tid & 31;
    const int vu8 = g_valid_u8;
    const int* __restrict__ v32 = (const int*)validp;
    const unsigned char* __restrict__ v8 = (const unsigned char*)validp;

    if (tid < COUT) { s_sum[tid] = 0.0f; s_ssq[tid] = 0.0f; }

    // copy W planes into SMEM (visibility covered by first tap __syncthreads)
    {
        const uint4* s = (const uint4*)g_wtf;
        uint4* d = (uint4*)smem;
        for (int i = tid; i < W_BYTES / 16; i += 256) d[i] = s[i];
    }

    // warp tiling: 4 m-slices x 2 n-slices of 32x32
    const int warp_m = warp & 3;
    const int warp_n = warp >> 2;
    // gather mapping: 2 threads per row
    const int rit  = tid >> 1;
    const int half = tid & 1;
    // lane-constant byte offsets
    const uint32_t aoff = (uint32_t)(warp_m * 32 * 32 + (lane >> 2) * 32 +
                                     (lane & 3) * 8);
    const uint32_t woff = (uint32_t)((warp_n * 32 + (lane >> 2)) * 32 +
                                     (lane & 3) * 8);

    // gather state (one tap ahead)
    int gtile = blockIdx.x, gtap = 0;
    float4 f[8];
    auto do_gather = [&]() {
        const int r = gtile * TILE_M + rit;
        bool live = false;
        const float4* src = nullptr;
        if (r < N) {
            const int vidx = r * KTAP + gtap;
            const bool v = vu8 ? (v8[vidx] != 0) : (v32[vidx] != 0);
            if (v) {
                live = true;
                src = (const float4*)(feats + (size_t)nidx[vidx] * CIN + half * 32);
            }
        }
        if (live) {
            #pragma unroll
            for (int j = 0; j < 8; j++) f[j] = src[j];
        } else {
            #pragma unroll
            for (int j = 0; j < 8; j++) f[j] = make_float4(0.f, 0.f, 0.f, 0.f);
        }
    };
    if (gtile < ntiles) do_gather();

    float st_sum[8], st_ssq[8];
    #pragma unroll
    for (int i = 0; i < 8; i++) { st_sum[i] = 0.f; st_ssq[i] = 0.f; }

    int parity = 0;

    for (int tile = blockIdx.x; tile < ntiles; tile += gridDim.x) {
        float C[2][4][4];
        #pragma unroll
        for (int mb = 0; mb < 2; mb++)
            #pragma unroll
            for (int nb = 0; nb < 4; nb++)
                #pragma unroll
                for (int q = 0; q < 4; q++) C[mb][nb][q] = 0.f;

        for (int tap = 0; tap < KTAP; tap++) {
            // ---- stage gathered rows as tf32 ----
            // cell [ks][row] holds 8 words; logical byte b stored at physical
            // b ^ (half*16) where half = (ks>>2). 2x STS.128 per ks per thread,
            // conflict-free: lane bank = rit*8 + half*4 (mod 32) is a perm.
            char* abuf = smem + SMEM_A + parity * APLANE;
            #pragma unroll
            for (int t2 = 0; t2 < 4; t2++) {
                const int ks = half * 4 + t2;
                const uint32_t base =
                    ((uint32_t)(ks * 4096 + rit * 32)) ^ ((uint32_t)half * 16u);
                float4 fa = f[2 * t2], fb = f[2 * t2 + 1];
                uint4 v0 = make_uint4(f2tf32(fa.x), f2tf32(fb.x),
                                      f2tf32(fa.y), f2tf32(fb.y));
                uint4 v1 = make_uint4(f2tf32(fa.z), f2tf32(fb.z),
                                      f2tf32(fa.w), f2tf32(fb.w));
                *(uint4*)(abuf + base) = v0;
                *(uint4*)(abuf + (base ^ 16u)) = v1;
            }
            __syncthreads();

            // ---- issue next gather (LDGs overlap the MMA block below) ----
            if (++gtap == KTAP) { gtap = 0; gtile += gridDim.x; }
            if (gtile < ntiles) do_gather();

            // ---- MMA: tf32 single pass ----
            const char* wbase = smem + tap * 16384;
            const char* abase = smem + SMEM_A + parity * APLANE;
            #pragma unroll
            for (int ks = 0; ks < 8; ks++) {
                const uint32_t swx = (uint32_t)(((ks >> 2) & 1) * 16);
                uint2 Wf[4];
                #pragma unroll
                for (int nb = 0; nb < 4; nb++)
                    Wf[nb] = *(const uint2*)(wbase + ks * 2048 + nb * 256 + woff);
                uint2 A02[2], A13[2];
                #pragma unroll
                for (int mb = 0; mb < 2; mb++) {
                    A02[mb] = *(const uint2*)(abase +
                        (((uint32_t)(ks * 4096 + mb * 512) + aoff) ^ swx));
                    A13[mb] = *(const uint2*)(abase +
                        (((uint32_t)(ks * 4096 + mb * 512 + 256) + aoff) ^ swx));
                }
                #pragma unroll
                for (int mb = 0; mb < 2; mb++)
                    #pragma unroll
                    for (int nb = 0; nb < 4; nb++)
                        mma_tf32(C[mb][nb], A02[mb].x, A13[mb].x,
                                 A02[mb].y, A13[mb].y, Wf[nb].x, Wf[nb].y);
            }
            parity ^= 1;
        }

        // ---- epilogue: store y, accumulate BN stats in regs ----
        {
            const int r0 = tile * TILE_M + warp_m * 32 + (lane >> 2);
            const int cbase = warp_n * 32 + (lane & 3) * 2;
            #pragma unroll
            for (int mb = 0; mb < 2; mb++) {
                const int ra = r0 + mb * 16;
                const int rb = ra + 8;
                #pragma unroll
                for (int nb = 0; nb < 4; nb++) {
                    const int c = cbase + nb * 8;
                    if (ra < N)
                        *(float2*)(g_y + (size_t)ra * COUT + c) =
                            make_float2(C[mb][nb][0], C[mb][nb][1]);
                    if (rb < N)
                        *(float2*)(g_y + (size_t)rb * COUT + c) =
                            make_float2(C[mb][nb][2], C[mb][nb][3]);
                    // rows >= N contributed zeros (gather zero-fill) -> no guard
                    st_sum[nb * 2 + 0] += C[mb][nb][0] + C[mb][nb][2];
                    st_sum[nb * 2 + 1] += C[mb][nb][1] + C[mb][nb][3];
                    st_ssq[nb * 2 + 0] += C[mb][nb][0] * C[mb][nb][0] +
                                          C[mb][nb][2] * C[mb][nb][2];
                    st_ssq[nb * 2 + 1] += C[mb][nb][1] * C[mb][nb][1] +
                                          C[mb][nb][3] * C[mb][nb][3];
                }
            }
        }
    }

    // ---- stats: regs -> smem -> global ----
    __syncthreads();
    {
        const int cbase = warp_n * 32 + (lane & 3) * 2;
        #pragma unroll
        for (int nb = 0; nb < 4; nb++) {
            atomicAdd(&s_sum[cbase + nb * 8 + 0], st_sum[nb * 2 + 0]);
            atomicAdd(&s_sum[cbase + nb * 8 + 1], st_sum[nb * 2 + 1]);
            atomicAdd(&s_ssq[cbase + nb * 8 + 0], st_ssq[nb * 2 + 0]);
            atomicAdd(&s_ssq[cbase + nb * 8 + 1], st_ssq[nb * 2 + 1]);
        }
    }
    __syncthreads();
    if (tid < COUT) {
        atomicAdd(&g_sum[tid], s_sum[tid]);
        atomicAdd(&g_ssq[tid], s_ssq[tid]);
    }
}

// ---------------- kernel: finalize BN scale/bias ----------------
__global__ void bn_finalize_kernel(const float* __restrict__ gamma,
                                   const float* __restrict__ beta, int N) {
    int c = threadIdx.x;
    if (c < COUT) {
        float inv_n = 1.0f / (float)N;
        float mean = g_sum[c] * inv_n;
        float var = g_ssq[c] * inv_n - mean * mean;
        float sc = gamma[c] * rsqrtf(var + EPS_BN);
        g_scale[c] = sc;
        g_bias[c] = beta[c] - mean * sc;
    }
}

// ---------------- kernel: apply BN + LeakyReLU ----------------
__global__ void __launch_bounds__(256)
apply_kernel(float* __restrict__ out, int total4) {
    __shared__ float ss[COUT];
    __shared__ float sb_[COUT];
    if (threadIdx.x < COUT) {
        ss[threadIdx.x] = g_scale[threadIdx.x];
        sb_[threadIdx.x] = g_bias[threadIdx.x];
    }
    __syncthreads();
    const float4* y4 = (const float4*)g_y;
    float4* o4 = (float4*)out;
    for (int i = blockIdx.x * blockDim.x + threadIdx.x; i < total4;
         i += gridDim.x * blockDim.x) {
        float4 y = y4[i];
        int c = (i & 15) * 4;
        float4 o;
        o.x = y.x * ss[c + 0] + sb_[c + 0];
        o.y = y.y * ss[c + 1] + sb_[c + 1];
        o.z = y.z * ss[c + 2] + sb_[c + 2];
        o.w = y.w * ss[c + 3] + sb_[c + 3];
        o.x = (o.x >= 0.f) ? o.x : LEAK * o.x;
        o.y = (o.y >= 0.f) ? o.y : LEAK * o.y;
        o.z = (o.z >= 0.f) ? o.z : LEAK * o.z;
        o.w = (o.w >= 0.f) ? o.w : LEAK * o.w;
        o4[i] = o;
    }
}

// ---------------- launch ----------------
extern "C" void kernel_launch(void* const* d_in, const int* in_sizes, int n_in,
                              void* d_out, int out_size) {
    const float* feats = (const float*)d_in[0];
    const float* W     = (const float*)d_in[1];
    const float* gamma = (const float*)d_in[2];
    const float* beta  = (const float*)d_in[3];
    const int*   nidx  = (const int*)d_in[4];
    const void*  valid = (const void*)d_in[5];

    const int N = in_sizes[0] / CIN;
    const int ntiles = (N + TILE_M - 1) / TILE_M;

    cudaFuncSetAttribute(conv_kernel,
                         cudaFuncAttributeMaxDynamicSharedMemorySize, CONV_SMEM);

    init_kernel<<<1, 256>>>((const unsigned int*)valid, 4096);   // launch 1
    prep_w_kernel<<<(KTAP * CIN * COUT + 255) / 256, 256>>>(W);  // launch 2
    pad_kernel<<<1, 32>>>();                                     // launch 3

    int grid = 152;
    if (grid > ntiles) grid = ntiles;
    conv_kernel<<<grid, 256, CONV_SMEM>>>(feats, nidx, valid, N, ntiles); // launch 4

    bn_finalize_kernel<<<1, 64>>>(gamma, beta, N);

    const int total4 = (N * COUT) / 4;
    apply_kernel<<<8192, 256>>>((float*)d_out, total4);
}

// round 15
// speedup vs baseline: 1.2267x; 1.2267x over previous
#include <cuda_runtime.h>
#include <cuda_bf16.h>
#include <cstdint>

#define CIN  64
#define COUT 64
#define KTAP 9
#define EPS_BN 1e-4f
#define LEAK 0.333f
#define MAX_N 1000000
#define TILE_M 128

// ---------------- global scratch ----------------
__device__ float g_y[(size_t)MAX_N * COUT];
__device__ float g_sum[COUT];
__device__ float g_ssq[COUT];
__device__ float g_scale[COUT];
__device__ float g_bias[COUT];
__device__ int   g_valid_u8;
// W as tf32, layout [tap][ks][n][p*2+e] : k = ks*8 + e*4 + p
__device__ uint32_t g_wtf[KTAP * 4096];

// ---------------- PTX helpers (portable sm_80-level only) ----------------
__device__ __forceinline__ uint32_t f2tf32(float x) {
    uint32_t u;
    asm("cvt.rna.tf32.f32 %0, %1;" : "=r"(u) : "f"(x));
    return u;
}
__device__ __forceinline__ void mma_tf32(float* c, uint32_t a0, uint32_t a1,
                                         uint32_t a2, uint32_t a3,
                                         uint32_t b0, uint32_t b1) {
    asm volatile(
        "mma.sync.aligned.m16n8k8.row.col.f32.tf32.tf32.f32 "
        "{%0,%1,%2,%3}, {%4,%5,%6,%7}, {%8,%9}, {%0,%1,%2,%3};"
        : "+f"(c[0]), "+f"(c[1]), "+f"(c[2]), "+f"(c[3])
        : "r"(a0), "r"(a1), "r"(a2), "r"(a3), "r"(b0), "r"(b1));
}

// ---------------- kernel: init (zero stats + detect valid dtype) ----------------
__global__ void init_kernel(const unsigned int* __restrict__ vwords, int nwords) {
    __shared__ int s_flag;
    int t = threadIdx.x;
    if (t == 0) s_flag = 0;
    if (t < COUT) { g_sum[t] = 0.0f; g_ssq[t] = 0.0f; }
    __syncthreads();
    int local = 0;
    for (int i = t; i < nwords; i += blockDim.x) {
        unsigned int w = vwords[i];
        if (w != 0u && w != 1u && w != 0x3F800000u) local = 1;
    }
    if (local) atomicOr(&s_flag, 1);
    __syncthreads();
    if (t == 0) g_valid_u8 = s_flag;
}

// ---------------- kernel: prep W (transpose + tf32 round + k-pair layout) ----------------
__global__ void prep_w_kernel(const float* __restrict__ W) {
    int i = blockIdx.x * blockDim.x + threadIdx.x;
    if (i >= KTAP * CIN * COUT) return;
    int t = i / (CIN * COUT);
    int rem = i % (CIN * COUT);
    int k = rem / COUT;           // ci
    int n = rem % COUT;
    int ks = k >> 3, r = k & 7, p = r & 3, e = r >> 2;
    g_wtf[t * 4096 + (ks * 64 + n) * 8 + p * 2 + e] = f2tf32(W[i]);
}

// ---------------- pad kernel (slot so ncu captures conv as launch 4) ----------------
__global__ void pad_kernel() {}

// ---------------- kernel: conv (warp-specialized mma.sync tf32) ----------------
#define W_BYTES   (KTAP * 16384)               // 147456
#define SMEM_A    W_BYTES
#define APLANE    32768                         // [8 ks][128 row][32B cell]
#define CONV_SMEM (SMEM_A + 2 * APLANE)         // 212992

__global__ void __launch_bounds__(256, 1)
conv_kernel(const float* __restrict__ feats,
            const int* __restrict__ nidx,
            const void* __restrict__ validp,
            int N, int ntiles) {
    extern __shared__ char smem[];
    __shared__ float s_sum[COUT];
    __shared__ float s_ssq[COUT];

    const int tid = threadIdx.x, warp = tid >> 5, lane = tid & 31;
    const int vu8 = g_valid_u8;
    const int* __restrict__ v32 = (const int*)validp;
    const unsigned char* __restrict__ v8 = (const unsigned char*)validp;

    if (tid < COUT) { s_sum[tid] = 0.0f; s_ssq[tid] = 0.0f; }

    // copy W planes into SMEM (visibility covered by first tap __syncthreads)
    {
        const uint4* s = (const uint4*)g_wtf;
        uint4* d = (uint4*)smem;
        for (int i = tid; i < W_BYTES / 16; i += 256) d[i] = s[i];
    }

    // ---- consumer setup (warps 0-3): 64 rows x 32 cols each ----
    const int warp_m = warp & 1;        // 2 m-slices of 64 rows
    const int warp_n = warp >> 1;       // 2 n-slices of 32 cols
    // A fragment lane offset; row-xor-16 is lane-constant: (row>>2)&1 == lane>>4
    const uint32_t aoff = (uint32_t)((lane >> 2) * 32 +
                          (((lane & 3) * 8) ^ ((lane >> 4) * 16)));
    const uint32_t woff = (uint32_t)((warp_n * 32 + (lane >> 2)) * 32 +
                                     (lane & 3) * 8);

    // ---- producer setup (warps 4-7): 1 thread per FULL row (64 floats) ----
    const int pr = tid - 128;           // row in tile (valid for tid>=128)
    const uint32_t xr_p = (uint32_t)(((pr >> 2) & 1) * 16);

    // producer gather state (one tap ahead); f holds the full 64-float row
    int gtile = blockIdx.x, gtap = 0;
    float4 f[16];
    auto do_gather = [&]() {
        const int r = gtile * TILE_M + pr;
        bool live = false;
        const float4* src = nullptr;
        if (r < N) {
            const int vidx = r * KTAP + gtap;
            const bool v = vu8 ? (v8[vidx] != 0) : (v32[vidx] != 0);
            if (v) {
                live = true;
                src = (const float4*)(feats + (size_t)nidx[vidx] * CIN);
            }
        }
        if (live) {
            #pragma unroll
            for (int j = 0; j < 16; j++) f[j] = src[j];
        } else {
            #pragma unroll
            for (int j = 0; j < 16; j++) f[j] = make_float4(0.f, 0.f, 0.f, 0.f);
        }
    };
    if (tid >= 128 && gtile < ntiles) do_gather();

    float st_sum[8], st_ssq[8];
    #pragma unroll
    for (int i = 0; i < 8; i++) { st_sum[i] = 0.f; st_ssq[i] = 0.f; }

    int p = 0;

    for (int tile = blockIdx.x; tile < ntiles; tile += gridDim.x) {
        float C[4][4][4];
        #pragma unroll
        for (int mb = 0; mb < 4; mb++)
            #pragma unroll
            for (int nb = 0; nb < 4; nb++)
                #pragma unroll
                for (int q = 0; q < 4; q++) C[mb][nb][q] = 0.f;

        for (int tap = 0; tap < KTAP; tap++) {
            if (tid >= 128) {
                // ---- producer: store f (this tap) into buf[p], then gather next
                char* abuf = smem + SMEM_A + p * APLANE;
                #pragma unroll
                for (int ks = 0; ks < 8; ks++) {
                    float4 fa = f[2 * ks], fb = f[2 * ks + 1];
                    uint4 v0 = make_uint4(f2tf32(fa.x), f2tf32(fb.x),
                                          f2tf32(fa.y), f2tf32(fb.y));
                    uint4 v1 = make_uint4(f2tf32(fa.z), f2tf32(fb.z),
                                          f2tf32(fa.w), f2tf32(fb.w));
                    const uint32_t base = (uint32_t)(ks * 4096 + pr * 32);
                    *(uint4*)(abuf + base + xr_p) = v0;
                    *(uint4*)(abuf + base + (xr_p ^ 16u)) = v1;
                }
                if (++gtap == KTAP) { gtap = 0; gtile += gridDim.x; }
                if (gtile < ntiles) do_gather();
            }
            __syncthreads();
            if (tid < 128) {
                // ---- consumer: MMA this tap from buf[p] ----
                const char* wbase = smem + tap * 16384;
                const char* abase = smem + SMEM_A + p * APLANE + warp_m * 2048;
                #pragma unroll
                for (int ks = 0; ks < 8; ks++) {
                    const char* wb = wbase + ks * 2048;
                    const char* ab = abase + ks * 4096;
                    uint2 Wf[4];
                    #pragma unroll
                    for (int nb = 0; nb < 4; nb++)
                        Wf[nb] = *(const uint2*)(wb + nb * 256 + woff);
                    #pragma unroll
                    for (int mb = 0; mb < 4; mb++) {
                        uint2 A02 = *(const uint2*)(ab + mb * 512 + aoff);
                        uint2 A13 = *(const uint2*)(ab + mb * 512 + 256 + aoff);
                        #pragma unroll
                        for (int nb = 0; nb < 4; nb++)
                            mma_tf32(C[mb][nb], A02.x, A13.x, A02.y, A13.y,
                                     Wf[nb].x, Wf[nb].y);
                    }
                }
            }
            p ^= 1;
        }

        // ---- consumer epilogue: store y, accumulate BN stats in regs ----
        if (tid < 128) {
            const int r0 = tile * TILE_M + warp_m * 64 + (lane >> 2);
            const int cbase = warp_n * 32 + (lane & 3) * 2;
            #pragma unroll
            for (int mb = 0; mb < 4; mb++) {
                const int ra = r0 + mb * 16;
                const int rb = ra + 8;
                #pragma unroll
                for (int nb = 0; nb < 4; nb++) {
                    const int c = cbase + nb * 8;
                    if (ra < N)
                        *(float2*)(g_y + (size_t)ra * COUT + c) =
                            make_float2(C[mb][nb][0], C[mb][nb][1]);
                    if (rb < N)
                        *(float2*)(g_y + (size_t)rb * COUT + c) =
                            make_float2(C[mb][nb][2], C[mb][nb][3]);
                    // rows >= N contributed zeros (gather zero-fill) -> no guard
                    st_sum[nb * 2 + 0] += C[mb][nb][0] + C[mb][nb][2];
                    st_sum[nb * 2 + 1] += C[mb][nb][1] + C[mb][nb][3];
                    st_ssq[nb * 2 + 0] += C[mb][nb][0] * C[mb][nb][0] +
                                          C[mb][nb][2] * C[mb][nb][2];
                    st_ssq[nb * 2 + 1] += C[mb][nb][1] * C[mb][nb][1] +
                                          C[mb][nb][3] * C[mb][nb][3];
                }
            }
        }
    }

    // ---- stats: consumer regs -> smem -> global ----
    __syncthreads();
    if (tid < 128) {
        const int cbase = warp_n * 32 + (lane & 3) * 2;
        #pragma unroll
        for (int nb = 0; nb < 4; nb++) {
            atomicAdd(&s_sum[cbase + nb * 8 + 0], st_sum[nb * 2 + 0]);
            atomicAdd(&s_sum[cbase + nb * 8 + 1], st_sum[nb * 2 + 1]);
            atomicAdd(&s_ssq[cbase + nb * 8 + 0], st_ssq[nb * 2 + 0]);
            atomicAdd(&s_ssq[cbase + nb * 8 + 1], st_ssq[nb * 2 + 1]);
        }
    }
    __syncthreads();
    if (tid < COUT) {
        atomicAdd(&g_sum[tid], s_sum[tid]);
        atomicAdd(&g_ssq[tid], s_ssq[tid]);
    }
}

// ---------------- kernel: finalize BN scale/bias ----------------
__global__ void bn_finalize_kernel(const float* __restrict__ gamma,
                                   const float* __restrict__ beta, int N) {
    int c = threadIdx.x;
    if (c < COUT) {
        float inv_n = 1.0f / (float)N;
        float mean = g_sum[c] * inv_n;
        float var = g_ssq[c] * inv_n - mean * mean;
        float sc = gamma[c] * rsqrtf(var + EPS_BN);
        g_scale[c] = sc;
        g_bias[c] = beta[c] - mean * sc;
    }
}

// ---------------- kernel: apply BN + LeakyReLU ----------------
__global__ void __launch_bounds__(256)
apply_kernel(float* __restrict__ out, int total4) {
    __shared__ float ss[COUT];
    __shared__ float sb_[COUT];
    if (threadIdx.x < COUT) {
        ss[threadIdx.x] = g_scale[threadIdx.x];
        sb_[threadIdx.x] = g_bias[threadIdx.x];
    }
    __syncthreads();
    const float4* y4 = (const float4*)g_y;
    float4* o4 = (float4*)out;
    for (int i = blockIdx.x * blockDim.x + threadIdx.x; i < total4;
         i += gridDim.x * blockDim.x) {
        float4 y = y4[i];
        int c = (i & 15) * 4;
        float4 o;
        o.x = y.x * ss[c + 0] + sb_[c + 0];
        o.y = y.y * ss[c + 1] + sb_[c + 1];
        o.z = y.z * ss[c + 2] + sb_[c + 2];
        o.w = y.w * ss[c + 3] + sb_[c + 3];
        o.x = (o.x >= 0.f) ? o.x : LEAK * o.x;
        o.y = (o.y >= 0.f) ? o.y : LEAK * o.y;
        o.z = (o.z >= 0.f) ? o.z : LEAK * o.z;
        o.w = (o.w >= 0.f) ? o.w : LEAK * o.w;
        o4[i] = o;
    }
}

// ---------------- launch ----------------
extern "C" void kernel_launch(void* const* d_in, const int* in_sizes, int n_in,
                              void* d_out, int out_size) {
    const float* feats = (const float*)d_in[0];
    const float* W     = (const float*)d_in[1];
    const float* gamma = (const float*)d_in[2];
    const float* beta  = (const float*)d_in[3];
    const int*   nidx  = (const int*)d_in[4];
    const void*  valid = (const void*)d_in[5];

    const int N = in_sizes[0] / CIN;
    const int ntiles = (N + TILE_M - 1) / TILE_M;

    cudaFuncSetAttribute(conv_kernel,
                         cudaFuncAttributeMaxDynamicSharedMemorySize, CONV_SMEM);

    init_kernel<<<1, 256>>>((const unsigned int*)valid, 4096);   // launch 1
    prep_w_kernel<<<(KTAP * CIN * COUT + 255) / 256, 256>>>(W);  // launch 2
    pad_kernel<<<1, 32>>>();                                     // launch 3

    int grid = 152;
    if (grid > ntiles) grid = ntiles;
    conv_kernel<<<grid, 256, CONV_SMEM>>>(feats, nidx, valid, N, ntiles); // launch 4

    bn_finalize_kernel<<<1, 64>>>(gamma, beta, N);

    const int total4 = (N * COUT) / 4;
    apply_kernel<<<8192, 256>>>((float*)d_out, total4);
}